// round 13
// baseline (speedup 1.0000x reference)
#include <cuda_runtime.h>
#include <cuda_fp16.h>
#include <math.h>

// OutputNetwork, fully factored pipeline:
//  K1 build_table: radial MLP tabulated on kink-aligned grid (h = step/12),
//     norms folded -> g_tab0[385][64], g_tab1[385][32], g_tab2[385][16] fp32.
//  K2 contract: G[zb][row][c] = sum_m T_part[row][m] * feats[z][b][map(c,m)]
//     for 9 channels, via fp16 mma.sync (fp32 accum), stored fp16
//     [zb][448][16] (58.7MB, L2-resident).
//  K3 main: per pair (z,a,b): segment-confined quintic weights, 6x32B G rows,
//     54 interp FMA + 8 Y-combine FMA; 16-lane butterfly -> softplus -> out.

#define NRR   385
#define GROWS 448

__device__ float  g_tab0[NRR * 64];
__device__ float  g_tab1[NRR * 32];
__device__ float  g_tab2[NRR * 16];
__device__ __half g_G[4096UL * GROWS * 16];   // [zb][row][16 ch]

// ---- build-kernel SMEM ----
#define BOFF_W2   0
#define BOFF_W3   16384
#define BOFF_H1   30720
#define BOFF_H2   31232
#define BSMEM_BYTES (31744 * 4)

// ---- contract-kernel SMEM (bytes) ----
#define CS_BYTES   131072            // Cs [64 b][64 row][16 half]
#define AS_OFF     131072            // As [64 b][K<=64] fp16
#define BS_OFF     139264            // Bs [64 row][K<=64] fp16
#define FS_OFF     147456
#define CT_SMEM    147472

__device__ __forceinline__ unsigned smem_u32(const void* p) {
    unsigned a;
    asm("{ .reg .u64 t; cvta.to.shared.u64 t, %1; cvt.u32.u64 %0, t; }" : "=r"(a) : "l"(p));
    return a;
}
__device__ __forceinline__ void ldm4(unsigned& r0, unsigned& r1, unsigned& r2, unsigned& r3,
                                     unsigned addr) {
    asm volatile("ldmatrix.sync.aligned.m8n8.x4.shared.b16 {%0, %1, %2, %3}, [%4];"
                 : "=r"(r0), "=r"(r1), "=r"(r2), "=r"(r3) : "r"(addr));
}
__device__ __forceinline__ void mma4(float* c, unsigned a0, unsigned a1, unsigned a2,
                                     unsigned a3, unsigned b0, unsigned b1) {
    asm volatile("mma.sync.aligned.m16n8k16.row.col.f32.f16.f16.f32 "
                 "{%0, %1, %2, %3}, {%4, %5, %6, %7}, {%8, %9}, {%0, %1, %2, %3};"
                 : "+f"(c[0]), "+f"(c[1]), "+f"(c[2]), "+f"(c[3])
                 : "r"(a0), "r"(a1), "r"(a2), "r"(a3), "r"(b0), "r"(b1));
}

__device__ __forceinline__ float ssp_precise(float x) {
    float bx = 5.0f * x;
    return (fmaxf(bx, 0.0f) + log1pf(expf(-fabsf(bx))) - 0.69314718055994531f) * 0.2f;
}

// ============================ K1: build table ============================
__global__ void __launch_bounds__(512, 1)
build_table_kernel(const float* __restrict__ W1,
                   const float* __restrict__ W2,
                   const float* __restrict__ W3)
{
    extern __shared__ float bs[];
    float* W2s = bs + (BOFF_W2 / 4) * 0;         // offsets in floats below
    float* W3s = bs + 16384;
    float* h1s = bs + 30720;
    float* h2s = bs + 31232;

    const int t  = threadIdx.x;
    const int rg = t >> 7;
    const int tl = t & 127;

    for (int i = t; i < 16384; i += 512) W2s[i] = W2[i];
    for (int i = t; i < 14336; i += 512) W3s[i] = W3[i];
    __syncthreads();

    const float RS32  = 0.17677669529663687f;
    const float RS128 = 0.08838834764831843f;

    #pragma unroll 1
    for (int qi = 0; qi < 2; qi++) {
        const int row = blockIdx.x * 8 + qi * 4 + rg;
        const bool live = (row < NRR);
        const float r = (float)row / 37.2f;

        float pre = 0.0f;
        #pragma unroll
        for (int kb = 0; kb < 32; kb++) {
            float d = r * 3.1f - (float)kb;
            float wv = (fabsf(d) < 1.0f) ? cosf(1.5707963267948966f * d) : 0.0f;
            pre += wv * W1[kb * 128 + tl];
        }
        h1s[rg * 128 + tl] = ssp_precise(pre * RS32);
        __syncthreads();

        float a2 = 0.0f;
        #pragma unroll 8
        for (int k = 0; k < 128; k++) a2 += h1s[rg * 128 + k] * W2s[k * 128 + tl];
        h2s[rg * 128 + tl] = ssp_precise(a2 * RS128);
        __syncthreads();

        if (live && tl < 112) {
            float a3 = 0.0f;
            #pragma unroll 8
            for (int k = 0; k < 128; k++) a3 += h2s[rg * 128 + k] * W3s[k * 112 + tl];
            const float norm = (tl < 64) ? 0.125f
                             : (tl < 96) ? 0.10206207261596575f
                                         : 0.11180339887498948f;
            const float val = a3 * RS128 * norm;
            if (tl < 64)      g_tab0[row * 64 + tl] = val;
            else if (tl < 96) g_tab1[row * 32 + (tl - 64)] = val;
            else              g_tab2[row * 16 + (tl - 96)] = val;
        }
        __syncthreads();
    }
}

// ============================ K2: contract (mma) ============================
__global__ void __launch_bounds__(512, 1)
contract_kernel(const float* __restrict__ rep,
                const float* __restrict__ mask)
{
    extern __shared__ char cs[];
    __half* Cs  = (__half*)cs;
    __half* As  = (__half*)(cs + AS_OFF);
    __half* Bs  = (__half*)(cs + BS_OFF);
    float*  fsS = (float*)(cs + FS_OFF);

    const int z  = blockIdx.y;
    const int rt = blockIdx.x;            // row tile 0..6 (64 rows each)
    const int t  = threadIdx.x;
    const int w  = t >> 5;
    const int lane = t & 31;

    if (t < 32) {
        float m = mask[z * 64 + t] + mask[z * 64 + 32 + t];
        #pragma unroll
        for (int o = 16; o > 0; o >>= 1) m += __shfl_xor_sync(0xffffffff, m, o);
        if (t == 0) fsS[0] = rsqrtf(m);
    }
    {
        uint4 zz = make_uint4(0, 0, 0, 0);
        uint4* c4 = (uint4*)Cs;
        for (int i = t; i < 8192; i += 512) c4[i] = zz;
    }
    __syncthreads();
    const float fs = fsS[0];

    const unsigned AsU = smem_u32(As);
    const unsigned BsU = smem_u32(Bs);

    const int mtile = w >> 2;            // 0..3  (b rows 16*mtile..)
    const int npair = w & 3;             // 0..3  (ntiles 2np, 2np+1)
    const int mi = lane >> 3, l7 = lane & 7;

    #pragma unroll 1
    for (int p = 0; p < 9; p++) {
        const int K      = (p == 0) ? 64 : ((p < 4) ? 32 : 16);
        const int kshift = (p == 0) ? 6  : ((p < 4) ? 5  : 4);
        const int fbase  = (p == 0) ? 0  : ((p < 4) ? 64 + (p - 1) : 160 + (p - 4));
        const int fstr   = (p == 0) ? 1  : ((p < 4) ? 3 : 5);
        const float* Tsrc = (p == 0) ? g_tab0 : ((p < 4) ? g_tab1 : g_tab2);

        // stage A (feats view, scaled) and B (table part)
        for (int i = t; i < 64 * K; i += 512) {
            const int b = i >> kshift, k = i & (K - 1);
            As[i] = __float2half_rn(fs * rep[(size_t)(z * 64 + b) * 240 + fbase + fstr * k]);
        }
        for (int i = t; i < 64 * K; i += 512) {
            const int n = i >> kshift, k = i & (K - 1);
            const int grow = rt * 64 + n;
            Bs[i] = (grow < NRR) ? __float2half_rn(Tsrc[grow * K + k]) : __half(0.0f);
        }
        __syncthreads();

        // mma: C[b][row] for this warp's 2 tiles
        float acc[2][4];
        #pragma unroll
        for (int i = 0; i < 2; i++) { acc[i][0] = 0.f; acc[i][1] = 0.f; acc[i][2] = 0.f; acc[i][3] = 0.f; }
        const int ar = mtile * 16 + (mi & 1) * 8 + l7;
        const int ac = (mi >> 1) * 8;
        const int bk = (mi & 1) * 8;
        const int bts = mi >> 1;
        #pragma unroll
        for (int ks = 0; ks < 4; ks++) {
            if (ks >= (K >> 4)) break;
            unsigned a0, a1, a2, a3;
            ldm4(a0, a1, a2, a3, AsU + (unsigned)((ar * K + ks * 16 + ac) * 2));
            unsigned r0, r1, r2, r3;
            ldm4(r0, r1, r2, r3,
                 BsU + (unsigned)((((2 * npair + bts) * 8 + l7) * K + ks * 16 + bk) * 2));
            mma4(acc[0], a0, a1, a2, a3, r0, r1);
            mma4(acc[1], a0, a1, a2, a3, r2, r3);
        }
        // fragments -> Cs[b][row][p]
        const int rb = lane >> 2, cq = lane & 3;
        #pragma unroll
        for (int nt2 = 0; nt2 < 2; nt2++) {
            const int n0 = (2 * npair + nt2) * 8 + 2 * cq;
            const int b0 = mtile * 16 + rb;
            Cs[(b0 * 64 + n0) * 16 + p]           = __float2half_rn(acc[nt2][0]);
            Cs[(b0 * 64 + n0 + 1) * 16 + p]       = __float2half_rn(acc[nt2][1]);
            Cs[((b0 + 8) * 64 + n0) * 16 + p]     = __float2half_rn(acc[nt2][2]);
            Cs[((b0 + 8) * 64 + n0 + 1) * 16 + p] = __float2half_rn(acc[nt2][3]);
        }
        __syncthreads();
    }

    // coalesced writeout: Cs[b][row][16] -> g_G[(z*64+b)*448 + rt*64 + row][16]
    const uint4* c4 = (const uint4*)Cs;
    uint4* g4 = (uint4*)g_G;
    for (int i = t; i < 8192; i += 512) {
        const int b = i >> 7, rem = i & 127;
        g4[((size_t)(z * 64 + b) * GROWS + rt * 64) * 2 + rem] = c4[i];
    }
}

// ============================ K3: main ============================
__global__ void __launch_bounds__(512, 1)
output_network_kernel(const float* __restrict__ geo,
                      const float* __restrict__ mask,
                      float* __restrict__ out)
{
    __shared__ float geoS[192];

    const int t  = threadIdx.x;
    const int z  = blockIdx.x >> 1;
    const int hf = blockIdx.x & 1;

    for (int i = t; i < 192; i += 512) geoS[i] = geo[z * 192 + i];
    __syncthreads();

    const int aloc = t >> 4;
    const int bq   = t & 15;
    const int a    = hf * 32 + aloc;
    const float gax = geoS[a * 3 + 0];
    const float gay = geoS[a * 3 + 1];
    const float gaz = geoS[a * 3 + 2];

    const float S3  = 1.7320508075688772f;
    const float S5  = 2.2360679774997896f;
    const float S15 = 3.872983346207417f;

    float wgt[4][6];
    int   gsv[4];
    float yv[4][8];

    // phase 1: geometry + quintic weights + Y for this thread's 4 pairs
    #pragma unroll
    for (int i = 0; i < 4; i++) {
        const int b = bq * 4 + i;
        const float rx = gax - geoS[b * 3 + 0];
        const float ry = gay - geoS[b * 3 + 1];
        const float rz = gaz - geoS[b * 3 + 2];
        const float r2 = rx * rx + ry * ry + rz * rz;
        const float r  = sqrtf(fmaxf(r2, 1e-12f));
        const float nz = (r2 > 1e-10f) ? 1.0f : 0.0f;
        const float inv = 1.0f / r;
        const float xh = rx * inv, yh = ry * inv, zh = rz * inv;
        yv[i][0] = S3 * xh * nz;
        yv[i][1] = S3 * yh * nz;
        yv[i][2] = S3 * zh * nz;
        yv[i][3] = S15 * xh * yh * nz;
        yv[i][4] = S15 * yh * zh * nz;
        yv[i][5] = 0.5f * S5 * (3.0f * zh * zh - 1.0f) * nz;
        yv[i][6] = S15 * xh * zh * nz;
        yv[i][7] = 0.5f * S15 * (xh * xh - yh * yh) * nz;

        float u = r * 37.2f;
        const float sup = (u < 384.0f) ? 1.0f : 0.0f;
        u = fminf(u, 383.99f);
        int sg = (int)(u * 0.0833333333f);
        sg = (sg > 31) ? 31 : sg;
        const float xi = u - 12.0f * (float)sg;
        int nl = (int)xi;
        int s0 = nl - 2;
        s0 = (s0 < 0) ? 0 : ((s0 > 7) ? 7 : s0);
        const float tt = xi - (float)s0;
        gsv[i] = 12 * sg + s0;

        const float p0 = tt,        p1 = tt - 1.0f, p2 = tt - 2.0f;
        const float p3 = tt - 3.0f, p4 = tt - 4.0f, p5 = tt - 5.0f;
        const float pr2 = p0 * p1, pr3 = pr2 * p2, pr4 = pr3 * p3, pr5 = pr4 * p4;
        const float sf3 = p4 * p5, sf2 = p3 * sf3, sf1 = p2 * sf2, sf0 = p1 * sf1;
        wgt[i][0] = sup * (-8.3333333333e-3f) * sf0;
        wgt[i][1] = sup * ( 4.1666666667e-2f) * p0 * sf1;
        wgt[i][2] = sup * (-8.3333333333e-2f) * pr2 * sf2;
        wgt[i][3] = sup * ( 8.3333333333e-2f) * pr3 * sf3;
        wgt[i][4] = sup * (-4.1666666667e-2f) * pr4 * p5;
        wgt[i][5] = sup * ( 8.3333333333e-3f) * pr5;
    }

    // phase 2: interpolate G rows and combine
    float tot = 0.0f;
    #pragma unroll
    for (int i = 0; i < 4; i++) {
        const int b = bq * 4 + i;
        const __half* hp = g_G + ((size_t)(z * 64 + b) * GROWS + gsv[i]) * 16;
        float R[9];
        #pragma unroll
        for (int c = 0; c < 9; c++) R[c] = 0.0f;
        #pragma unroll
        for (int k = 0; k < 6; k++) {
            const uint4 v  = *(const uint4*)(hp + k * 16);
            const unsigned v8 = *(const unsigned*)(hp + k * 16 + 8);
            const float wk = wgt[i][k];
            float2 c01 = __half22float2(*(const __half2*)&v.x);
            float2 c23 = __half22float2(*(const __half2*)&v.y);
            float2 c45 = __half22float2(*(const __half2*)&v.z);
            float2 c67 = __half22float2(*(const __half2*)&v.w);
            float2 c8x = __half22float2(*(const __half2*)&v8);
            R[0] = fmaf(wk, c01.x, R[0]);
            R[1] = fmaf(wk, c01.y, R[1]);
            R[2] = fmaf(wk, c23.x, R[2]);
            R[3] = fmaf(wk, c23.y, R[3]);
            R[4] = fmaf(wk, c45.x, R[4]);
            R[5] = fmaf(wk, c45.y, R[5]);
            R[6] = fmaf(wk, c67.x, R[6]);
            R[7] = fmaf(wk, c67.y, R[7]);
            R[8] = fmaf(wk, c8x.x, R[8]);
        }
        float ct = R[0];
        ct = fmaf(yv[i][0], R[1], ct);
        ct = fmaf(yv[i][1], R[2], ct);
        ct = fmaf(yv[i][2], R[3], ct);
        ct = fmaf(yv[i][3], R[4], ct);
        ct = fmaf(yv[i][4], R[5], ct);
        ct = fmaf(yv[i][5], R[6], ct);
        ct = fmaf(yv[i][6], R[7], ct);
        ct = fmaf(yv[i][7], R[8], ct);
        tot += ct;
    }

    // 16-lane butterfly (threads sharing this a) -> softplus -> out
    tot += __shfl_xor_sync(0xffffffff, tot, 1);
    tot += __shfl_xor_sync(0xffffffff, tot, 2);
    tot += __shfl_xor_sync(0xffffffff, tot, 4);
    tot += __shfl_xor_sync(0xffffffff, tot, 8);
    if (bq == 0) {
        const float bx = 5.0f * tot;
        const float sp = (fmaxf(bx, 0.0f) + log1pf(expf(-fabsf(bx)))) * 0.2f;
        out[z * 64 + a] = sp * mask[z * 64 + a];
    }
}

extern "C" void kernel_launch(void* const* d_in, const int* in_sizes, int n_in,
                              void* d_out, int out_size)
{
    const float* rep  = (const float*)d_in[0];
    const float* geo  = (const float*)d_in[1];
    const float* mask = (const float*)d_in[2];
    const float* W1   = (const float*)d_in[3];
    const float* W2   = (const float*)d_in[4];
    const float* W3   = (const float*)d_in[5];
    float* out = (float*)d_out;

    cudaFuncSetAttribute(build_table_kernel,
                         cudaFuncAttributeMaxDynamicSharedMemorySize, BSMEM_BYTES);
    cudaFuncSetAttribute(contract_kernel,
                         cudaFuncAttributeMaxDynamicSharedMemorySize, CT_SMEM);

    build_table_kernel<<<49, 512, BSMEM_BYTES>>>(W1, W2, W3);
    contract_kernel<<<dim3(7, 64), 512, CT_SMEM>>>(rep, mask);
    output_network_kernel<<<128, 512>>>(geo, mask, out);
}